// round 10
// baseline (speedup 1.0000x reference)
#include <cuda_runtime.h>
#include <cuda_bf16.h>
#include <cstdint>

// SSIM loss map: out = clip((1 - SSIM_3x3(x,y)) * 0.5, 0, 1)
// NCHW fp32, 16x3x512x512 = 48 planes of 512x512.
// Register-sliding, no shared memory. Each thread owns FOUR columns
// (float4); all horizontal stats are computed in packed f32x2 form via
// shared shifted vectors. One-iteration software pipeline; rolling vertical
// window compressed to (p+c, c). Clamp folded into FFMA.SAT.

#define IMG   512
#define ROWS  16          // output rows per thread
#define TPX   128         // threads per block; TPX*4 == IMG (full row)

typedef unsigned long long u64;

// ---- packed f32x2 helpers (sm_100+) ----
__device__ __forceinline__ u64 pk(float x, float y) {
    u64 r; asm("mov.b64 %0, {%1, %2};" : "=l"(r) : "f"(x), "f"(y)); return r;
}
__device__ __forceinline__ float2 unpk(u64 v) {
    float2 r; asm("mov.b64 {%0, %1}, %2;" : "=f"(r.x), "=f"(r.y) : "l"(v)); return r;
}
__device__ __forceinline__ u64 add2(u64 a, u64 b) {
    u64 r; asm("add.rn.f32x2 %0, %1, %2;" : "=l"(r) : "l"(a), "l"(b)); return r;
}
__device__ __forceinline__ u64 sub2(u64 a, u64 b) {
    u64 r; asm("sub.rn.f32x2 %0, %1, %2;" : "=l"(r) : "l"(a), "l"(b)); return r;
}
__device__ __forceinline__ u64 mul2(u64 a, u64 b) {
    u64 r; asm("mul.rn.f32x2 %0, %1, %2;" : "=l"(r) : "l"(a), "l"(b)); return r;
}
__device__ __forceinline__ u64 fma2(u64 a, u64 b, u64 c) {
    u64 r; asm("fma.rn.f32x2 %0, %1, %2, %3;" : "=l"(r) : "l"(a), "l"(b), "l"(c)); return r;
}

// Raw row: this thread's float4 of x and y + prefetched edge neighbor
// scalars (meaningful only in lanes 0 / 31).
struct Raw { float4 a, b; float eLa, eLb, eRa, eRb; };

// Horizontal 3-tap sums for the 4 output columns: two packed pairs per stat.
struct Stat { u64 x01, x23, y01, y23, xx01, xx23, yy01, yy23, xy01, xy23; };

// Prefetch: LDGs only; doff is compile-time-constant at every call site.
__device__ __forceinline__ Raw load_raw(const float* __restrict__ px,
                                        const float* __restrict__ py,
                                        int doff, bool valid,
                                        bool doL, bool doR)
{
    Raw r;
    r.a = make_float4(0.f, 0.f, 0.f, 0.f);
    r.b = make_float4(0.f, 0.f, 0.f, 0.f);
    r.eLa = r.eLb = r.eRa = r.eRb = 0.f;
    if (valid) {
        r.a = *(const float4*)(px + doff);
        r.b = *(const float4*)(py + doff);
        if (doL) { r.eLa = px[doff - 1]; r.eLb = py[doff - 1]; }
        if (doR) { r.eRa = px[doff + 4]; r.eRb = py[doff + 4]; }
    }
    return r;
}

// Consume: shuffles on registers loaded >= 1 iteration ago; packed h-stats
// built from shared shifted vectors (vB reused by both column pairs).
__device__ __forceinline__ Stat make_stats(const Raw& w, bool pl, bool pr)
{
    float aL = __shfl_up_sync(0xffffffffu, w.a.w, 1);
    float bL = __shfl_up_sync(0xffffffffu, w.b.w, 1);
    float aR = __shfl_down_sync(0xffffffffu, w.a.x, 1);
    float bR = __shfl_down_sync(0xffffffffu, w.b.x, 1);
    if (pl) { aL = w.eLa; bL = w.eLb; }
    if (pr) { aR = w.eRa; bR = w.eRb; }

    // packed views of the 4 columns and the shifted neighbor vectors
    u64 uA01 = pk(w.a.x, w.a.y), uA23 = pk(w.a.z, w.a.w);
    u64 uB01 = pk(w.b.x, w.b.y), uB23 = pk(w.b.z, w.b.w);
    u64 vA = pk(aL, w.a.x), vB = pk(w.a.y, w.a.z), vC = pk(w.a.w, aR);
    u64 vD = pk(bL, w.b.x), vE = pk(w.b.y, w.b.z), vF = pk(w.b.w, bR);

    Stat s;
    s.x01  = add2(vA, add2(uA01, vB));
    s.x23  = add2(vB, add2(uA23, vC));
    s.y01  = add2(vD, add2(uB01, vE));
    s.y23  = add2(vE, add2(uB23, vF));
    s.xx01 = fma2(vA, vA, fma2(vB, vB, mul2(uA01, uA01)));
    s.xx23 = fma2(vB, vB, fma2(vC, vC, mul2(uA23, uA23)));
    s.yy01 = fma2(vD, vD, fma2(vE, vE, mul2(uB01, uB01)));
    s.yy23 = fma2(vE, vE, fma2(vF, vF, mul2(uB23, uB23)));
    s.xy01 = fma2(vA, vD, fma2(vB, vE, mul2(uA01, uB01)));
    s.xy23 = fma2(vB, vE, fma2(vC, vF, mul2(uA23, uB23)));
    return s;
}

// normalized SSIM epilogue for one packed column pair -> two outputs
__device__ __forceinline__ void ssim_pair(u64 Sx, u64 Sy, u64 Sxx, u64 Syy,
                                          u64 Sxy, u64 inv,
                                          u64 TWO2, u64 C12, u64 C22,
                                          float* o0, float* o1)
{
    u64 mux = mul2(Sx, inv);
    u64 muy = mul2(Sy, inv);
    u64 mmx  = mul2(mux, mux);
    u64 mmy  = mul2(muy, muy);
    u64 mmxy = mul2(mux, muy);
    u64 sigx  = sub2(mul2(Sxx, inv), mmx);
    u64 sigy  = sub2(mul2(Syy, inv), mmy);
    u64 sigxy = sub2(mul2(Sxy, inv), mmxy);

    u64 t1  = fma2(mmxy, TWO2, C12);
    u64 t2  = fma2(sigxy, TWO2, C22);
    u64 num = mul2(t1, t2);
    u64 d1  = add2(add2(mmx, mmy), C12);
    u64 d2  = add2(add2(sigx, sigy), C22);
    u64 den = mul2(d1, d2);          // +1e-12 is below fp32 ulp of den here

    float2 fn = unpk(num);
    float2 fd = unpk(den);
    *o0 = __saturatef(fmaf(__fdividef(fn.x, fd.x), -0.5f, 0.5f));
    *o1 = __saturatef(fmaf(__fdividef(fn.y, fd.y), -0.5f, 0.5f));
}

__global__ __launch_bounds__(TPX)
void ssim_kernel(const float* __restrict__ gx,
                 const float* __restrict__ gy,
                 float* __restrict__ gout)
{
    const int tx   = threadIdx.x;              // owns cols [4tx, 4tx+3]
    const int lane = tx & 31;
    const bool pl = (lane == 0);
    const bool pr = (lane == 31);
    const bool doL = pl && (tx > 0);
    const bool doR = pr && (tx < TPX - 1);
    const int h0 = blockIdx.y * ROWS;

    const size_t base = (size_t)blockIdx.z * (IMG * IMG);
    const int toff = h0 * IMG + 4 * tx;
    const float* px = gx + base + toff;
    const float* py = gy + base + toff;
    float4* pout = (float4*)(gout + base) + (h0 * (IMG / 4) + tx);

    const float THIRD = 1.f / 3.f;
    const float cx0 = (tx == 0) ? 0.5f : THIRD;         // reciprocal tap count
    const float cx3 = (tx == TPX - 1) ? 0.5f : THIRD;

    const u64 TWO2 = pk(2.f, 2.f);
    const u64 C12  = pk(1e-4f, 1e-4f);
    const u64 C22  = pk(9e-4f, 9e-4f);
    const u64 inv01_i = pk(cx0 * THIRD, THIRD * THIRD); // interior rows
    const u64 inv23_i = pk(THIRD * THIRD, cx3 * THIRD);

    // Pipeline fill. Rolling state: pc = stats(h-1)+stats(h), c = stats(h).
    Stat p0 = make_stats(load_raw(px, py, -IMG, h0 > 0, doL, doR), pl, pr);
    Stat c  = make_stats(load_raw(px, py, 0, true, doL, doR), pl, pr);
    Stat pc;
    pc.x01 = add2(p0.x01, c.x01);  pc.x23 = add2(p0.x23, c.x23);
    pc.y01 = add2(p0.y01, c.y01);  pc.y23 = add2(p0.y23, c.y23);
    pc.xx01 = add2(p0.xx01, c.xx01); pc.xx23 = add2(p0.xx23, c.xx23);
    pc.yy01 = add2(p0.yy01, c.yy01); pc.yy23 = add2(p0.yy23, c.yy23);
    pc.xy01 = add2(p0.xy01, c.xy01); pc.xy23 = add2(p0.xy23, c.xy23);
    Raw rn = load_raw(px, py, IMG, true, doL, doR);

    #pragma unroll
    for (int r = 0; r < ROWS; r++) {
        // prefetch row h0+r+2 (in-bounds except last 2 iters of last y-block)
        const bool valid = (r < ROWS - 2) || (h0 < IMG - ROWS);
        Raw rf = load_raw(px, py, (r + 2) * IMG, valid, doL, doR);

        // consume the row prefetched last iteration
        Stat n = make_stats(rn, pl, pr);

        // normalization: cy != 3 only possible at iterations 0 and ROWS-1
        u64 inv01 = inv01_i, inv23 = inv23_i;
        if ((r == 0 && h0 == 0) || (r == ROWS - 1 && h0 == IMG - ROWS)) {
            inv01 = pk(cx0 * 0.5f, THIRD * 0.5f);
            inv23 = pk(THIRD * 0.5f, cx3 * 0.5f);
        }

        // vertical 3-tap totals and window shift
        u64 Sx01 = add2(pc.x01, n.x01),   Sx23 = add2(pc.x23, n.x23);
        u64 Sy01 = add2(pc.y01, n.y01),   Sy23 = add2(pc.y23, n.y23);
        u64 Sxx01 = add2(pc.xx01, n.xx01), Sxx23 = add2(pc.xx23, n.xx23);
        u64 Syy01 = add2(pc.yy01, n.yy01), Syy23 = add2(pc.yy23, n.yy23);
        u64 Sxy01 = add2(pc.xy01, n.xy01), Sxy23 = add2(pc.xy23, n.xy23);

        pc.x01 = add2(c.x01, n.x01);   pc.x23 = add2(c.x23, n.x23);
        pc.y01 = add2(c.y01, n.y01);   pc.y23 = add2(c.y23, n.y23);
        pc.xx01 = add2(c.xx01, n.xx01); pc.xx23 = add2(c.xx23, n.xx23);
        pc.yy01 = add2(c.yy01, n.yy01); pc.yy23 = add2(c.yy23, n.yy23);
        pc.xy01 = add2(c.xy01, n.xy01); pc.xy23 = add2(c.xy23, n.xy23);
        c = n;

        float4 o;
        ssim_pair(Sx01, Sy01, Sxx01, Syy01, Sxy01, inv01,
                  TWO2, C12, C22, &o.x, &o.y);
        ssim_pair(Sx23, Sy23, Sxx23, Syy23, Sxy23, inv23,
                  TWO2, C12, C22, &o.z, &o.w);

        pout[r * (IMG / 4)] = o;

        rn = rf;
    }
}

extern "C" void kernel_launch(void* const* d_in, const int* in_sizes, int n_in,
                              void* d_out, int out_size)
{
    const float* x = (const float*)d_in[0];
    const float* y = (const float*)d_in[1];
    float* out = (float*)d_out;

    dim3 block(TPX, 1, 1);                    // 128 threads = full row width
    dim3 grid(1, IMG / ROWS, 16 * 3);         // 1 x 32 x 48 = 1536 blocks
    ssim_kernel<<<grid, block>>>(x, y, out);
}

// round 11
// speedup vs baseline: 1.2746x; 1.2746x over previous
#include <cuda_runtime.h>
#include <cuda_bf16.h>
#include <cstdint>

// SSIM loss map: out = clip((1 - SSIM_3x3(x,y)) * 0.5, 0, 1)
// NCHW fp32, 16x3x512x512 = 48 planes of 512x512.
// Register-sliding, no shared memory, NO SHUFFLES: each thread loads three
// aligned float2s per image per row (left/mid/right) so all horizontal taps
// are thread-local; the overlap is served by L1. Packed f32x2 math,
// one-iteration software pipeline, (p+c, c) rolling vertical window,
// pointer + compile-time-constant addressing.

#define IMG   512
#define ROWS  16          // output rows per thread
#define TPX   128         // threads per block; block covers TPX*2 = 256 cols

typedef unsigned long long u64;

// ---- packed f32x2 helpers (sm_100+) ----
__device__ __forceinline__ u64 pk(float x, float y) {
    u64 r; asm("mov.b64 %0, {%1, %2};" : "=l"(r) : "f"(x), "f"(y)); return r;
}
__device__ __forceinline__ float2 unpk(u64 v) {
    float2 r; asm("mov.b64 {%0, %1}, %2;" : "=f"(r.x), "=f"(r.y) : "l"(v)); return r;
}
__device__ __forceinline__ u64 add2(u64 a, u64 b) {
    u64 r; asm("add.rn.f32x2 %0, %1, %2;" : "=l"(r) : "l"(a), "l"(b)); return r;
}
__device__ __forceinline__ u64 sub2(u64 a, u64 b) {
    u64 r; asm("sub.rn.f32x2 %0, %1, %2;" : "=l"(r) : "l"(a), "l"(b)); return r;
}
__device__ __forceinline__ u64 mul2(u64 a, u64 b) {
    u64 r; asm("mul.rn.f32x2 %0, %1, %2;" : "=l"(r) : "l"(a), "l"(b)); return r;
}
__device__ __forceinline__ u64 fma2(u64 a, u64 b, u64 c) {
    u64 r; asm("fma.rn.f32x2 %0, %1, %2, %3;" : "=l"(r) : "l"(a), "l"(b), "l"(c)); return r;
}

// Raw row: mid pair + left/right neighbor pairs for both images.
// Used taps: aL.y, aM.x, aM.y, aR.x (same for b).
struct Raw { float2 aL, aM, aR, bL, bM, bR; };

// Horizontal 3-tap sums for the thread's 2 output columns, packed f32x2.
struct Stat { u64 x, y, xx, yy, xy; };

// Prefetch: LDGs only; doff is compile-time-constant at every call site.
__device__ __forceinline__ Raw load_raw(const float* __restrict__ px,
                                        const float* __restrict__ py,
                                        int doff, bool valid,
                                        bool okL, bool okR)
{
    Raw r;
    r.aL = r.aM = r.aR = make_float2(0.f, 0.f);
    r.bL = r.bM = r.bR = make_float2(0.f, 0.f);
    if (valid) {
        r.aM = *(const float2*)(px + doff);
        r.bM = *(const float2*)(py + doff);
        if (okL) {                              // aligned: col 2c2-2 is even
            r.aL = *(const float2*)(px + doff - 2);
            r.bL = *(const float2*)(py + doff - 2);
        }
        if (okR) {
            r.aR = *(const float2*)(px + doff + 2);
            r.bR = *(const float2*)(py + doff + 2);
        }
    }
    return r;
}

// Consume: pure register math on data loaded >= 1 iteration ago.
__device__ __forceinline__ Stat make_stats(const Raw& w)
{
    const float aL = w.aL.y, aR = w.aR.x;
    const float bL = w.bL.y, bR = w.bR.x;

    Stat s;
    float sa = w.aM.x + w.aM.y;
    s.x = pk(aL + sa, sa + aR);
    float sb = w.bM.x + w.bM.y;
    s.y = pk(bL + sb, sb + bR);
    float pa = fmaf(w.aM.x, w.aM.x, w.aM.y * w.aM.y);
    s.xx = pk(fmaf(aL, aL, pa), fmaf(aR, aR, pa));
    float pb = fmaf(w.bM.x, w.bM.x, w.bM.y * w.bM.y);
    s.yy = pk(fmaf(bL, bL, pb), fmaf(bR, bR, pb));
    float pm = fmaf(w.aM.x, w.bM.x, w.aM.y * w.bM.y);
    s.xy = pk(fmaf(aL, bL, pm), fmaf(aR, bR, pm));
    return s;
}

__global__ __launch_bounds__(TPX)
void ssim_kernel(const float* __restrict__ gx,
                 const float* __restrict__ gy,
                 float* __restrict__ gout)
{
    const int tx = threadIdx.x;
    const int c2 = blockIdx.x * TPX + tx;       // float2 column index, 0..255
    const bool okL = (c2 > 0);
    const bool okR = (c2 < IMG / 2 - 1);
    const int h0 = blockIdx.y * ROWS;

    // per-thread base pointers at (row h0, col 2*c2); all further addressing
    // is compile-time-constant offsets from these
    const size_t base = (size_t)blockIdx.z * (IMG * IMG);
    const int toff = h0 * IMG + 2 * c2;
    const float* px = gx + base + toff;
    const float* py = gy + base + toff;
    float2* pout = (float2*)(gout + base) + (h0 * (IMG / 2) + c2);

    const float THIRD = 1.f / 3.f;
    float2 rcx = make_float2(okL ? THIRD : 0.5f,
                             okR ? THIRD : 0.5f);

    const u64 TWO2 = pk(2.f, 2.f);
    const u64 C12  = pk(1e-4f, 1e-4f);
    const u64 C22  = pk(9e-4f, 9e-4f);
    const u64 inv3 = pk(rcx.x * THIRD, rcx.y * THIRD);   // interior rows

    // Pipeline fill. Rolling state: pc = stats(h-1)+stats(h), c = stats(h).
    Stat p0 = make_stats(load_raw(px, py, -IMG, h0 > 0, okL, okR));
    Stat c  = make_stats(load_raw(px, py, 0, true, okL, okR));
    Stat pc;
    pc.x  = add2(p0.x,  c.x);
    pc.y  = add2(p0.y,  c.y);
    pc.xx = add2(p0.xx, c.xx);
    pc.yy = add2(p0.yy, c.yy);
    pc.xy = add2(p0.xy, c.xy);
    Raw rn = load_raw(px, py, IMG, true, okL, okR);

    #pragma unroll
    for (int r = 0; r < ROWS; r++) {
        // prefetch row h0+r+2: in-bounds by construction except the last two
        // iterations of the last y-block (compile-time except the h0 compare)
        const bool valid = (r < ROWS - 2) || (h0 < IMG - ROWS);
        Raw rf = load_raw(px, py, (r + 2) * IMG, valid, okL, okR);

        // consume the row prefetched last iteration (registers only)
        Stat n = make_stats(rn);

        // normalization: cy != 3 only possible at iterations 0 and ROWS-1
        u64 inv = inv3;
        if ((r == 0 && h0 == 0) || (r == ROWS - 1 && h0 == IMG - ROWS))
            inv = pk(rcx.x * 0.5f, rcx.y * 0.5f);

        // vertical 3-tap totals and window shift
        u64 Sx  = add2(pc.x,  n.x);
        u64 Sy  = add2(pc.y,  n.y);
        u64 Sxx = add2(pc.xx, n.xx);
        u64 Syy = add2(pc.yy, n.yy);
        u64 Sxy = add2(pc.xy, n.xy);

        pc.x  = add2(c.x,  n.x);
        pc.y  = add2(c.y,  n.y);
        pc.xx = add2(c.xx, n.xx);
        pc.yy = add2(c.yy, n.yy);
        pc.xy = add2(c.xy, n.xy);
        c = n;

        // packed SSIM epilogue
        u64 mux = mul2(Sx, inv);
        u64 muy = mul2(Sy, inv);
        u64 mmx  = mul2(mux, mux);
        u64 mmy  = mul2(muy, muy);
        u64 mmxy = mul2(mux, muy);
        u64 sigx  = sub2(mul2(Sxx, inv), mmx);
        u64 sigy  = sub2(mul2(Syy, inv), mmy);
        u64 sigxy = sub2(mul2(Sxy, inv), mmxy);

        u64 t1  = fma2(mmxy, TWO2, C12);
        u64 t2  = fma2(sigxy, TWO2, C22);
        u64 num = mul2(t1, t2);
        u64 d1  = add2(add2(mmx, mmy), C12);
        u64 d2  = add2(add2(sigx, sigy), C22);
        u64 den = mul2(d1, d2);       // den >= C1*C2 >> 1e-12; eps is sub-ulp

        float2 fn = unpk(num);
        float2 fd = unpk(den);
        float2 o;
        o.x = __saturatef(fmaf(__fdividef(fn.x, fd.x), -0.5f, 0.5f));
        o.y = __saturatef(fmaf(__fdividef(fn.y, fd.y), -0.5f, 0.5f));

        pout[r * (IMG / 2)] = o;

        rn = rf;
    }
}

extern "C" void kernel_launch(void* const* d_in, const int* in_sizes, int n_in,
                              void* d_out, int out_size)
{
    const float* x = (const float*)d_in[0];
    const float* y = (const float*)d_in[1];
    float* out = (float*)d_out;

    dim3 block(TPX, 1, 1);                            // 128 threads
    dim3 grid(IMG / (2 * TPX), IMG / ROWS, 16 * 3);   // 2 x 32 x 48 = 3072
    ssim_kernel<<<grid, block>>>(x, y, out);
}